// round 17
// baseline (speedup 1.0000x reference)
#include <cuda_runtime.h>
#include <cuda_bf16.h>
#include <math_constants.h>

// Shapes (fixed for this problem)
#define B  32
#define S  4096
#define H  1024
#define D  2048   // 2*H

#define HS 16           // h-splits for vpart
#define HC (H / HS)     // 64 h per split
#define BG 8            // batches per vpart CTA

#define TOTROWS (B * S)          // 131072 flattened rows
#define NCTA_E  1824             // exactly 4 waves of 152 SMs * 3 CTAs (GB300)
#define NWARP_E (NCTA_E * 16)    // 29184 warps

#define SCHUNK 8                 // softmax chunks per batch (512 elems each)

// Scratch (device globals; no allocation allowed)
__device__ float g_vpart[HS][B * D];  // h-split partials of v = W^T hidden
__device__ float g_v[B * D];
__device__ float g_energy[B * S];
__device__ float g_pm[B][SCHUNK];     // per-chunk max
__device__ float g_ps[B][SCHUNK];     // per-chunk sum

// ---------------------------------------------------------------------------
// Kernel 1: v_part[hs][b][d] = sum_{h in chunk hs} hidden[b][h] * W[h][d]
// grid (D/128, B/8, HS) = 1024 CTAs, block 128. hsm transposed: the 8 batch
// values per iter come from 2 LDS.128.
// ---------------------------------------------------------------------------
__global__ __launch_bounds__(128) void k_vpart(const float* __restrict__ hidden,
                                               const float* __restrict__ W) {
    const int tid = threadIdx.x;
    const int d   = blockIdx.x * 128 + tid;
    const int bg  = blockIdx.y;           // batch group of 8
    const int hs  = blockIdx.z;           // h chunk of HC

    __shared__ float4 hsm4[HC][2];        // [hl][jj] : 8 batches as 2 float4
    for (int idx = tid; idx < BG * HC; idx += 128) {
        int j = idx & 7, hl = idx >> 3;
        reinterpret_cast<float*>(hsm4)[hl * 8 + j] =
            hidden[(bg * BG + j) * H + hs * HC + hl];
    }
    __syncthreads();

    float acc[8];
#pragma unroll
    for (int j = 0; j < 8; ++j) acc[j] = 0.f;

    const float* Wp = W + (size_t)(hs * HC) * D + d;
#pragma unroll 16
    for (int hl = 0; hl < HC; ++hl) {
        float w = Wp[(size_t)hl * D];
        float4 h0 = hsm4[hl][0];
        float4 h1 = hsm4[hl][1];
        acc[0] += h0.x * w;  acc[1] += h0.y * w;
        acc[2] += h0.z * w;  acc[3] += h0.w * w;
        acc[4] += h1.x * w;  acc[5] += h1.y * w;
        acc[6] += h1.z * w;  acc[7] += h1.w * w;
    }

#pragma unroll
    for (int j = 0; j < 8; ++j)
        g_vpart[hs][(bg * BG + j) * D + d] = acc[j];
}

// ---------------------------------------------------------------------------
// Kernel 1b: v = sum of HS partials, float4-vectorized (deterministic)
// ---------------------------------------------------------------------------
__global__ void k_vreduce() {
    int idx = blockIdx.x * blockDim.x + threadIdx.x;   // B*D/4 threads
    if (idx < B * D / 4) {
        float4 s = make_float4(0.f, 0.f, 0.f, 0.f);
#pragma unroll
        for (int p = 0; p < HS; ++p) {
            float4 a = reinterpret_cast<const float4*>(g_vpart[p])[idx];
            s.x += a.x; s.y += a.y; s.z += a.z; s.w += a.w;
        }
        reinterpret_cast<float4*>(g_v)[idx] = s;
    }
}

// ---------------------------------------------------------------------------
// Kernel 2: energies[row] = dot(enc[row][:], v[row>>12][:])
// Flat warp-granular split, no smem, v via __ldg (L1-resident after first
// row). 1824 CTAs = exactly 4 waves on GB300's 152 SMs x 3 CTAs (1776 was
// sized for 148 SMs -> 3.89 waves, ~11% idle last wave).
// ---------------------------------------------------------------------------
__global__ __launch_bounds__(512, 3) void k_energy(const float* __restrict__ enc) {
    const int  lane = threadIdx.x & 31;
    const long gw   = (long)blockIdx.x * 16 + (threadIdx.x >> 5);

    const int r0 = (int)((gw * (long)TOTROWS) / NWARP_E);
    const int r1 = (int)(((gw + 1) * (long)TOTROWS) / NWARP_E);

    for (int r = r0; r < r1; ++r) {
        const float4* v4 = reinterpret_cast<const float4*>(
            g_v + (size_t)(r >> 12) * D);
        const float4* e4 = reinterpret_cast<const float4*>(
            enc + (size_t)r * D);
        float acc = 0.f;
#pragma unroll
        for (int i = 0; i < 16; ++i) {
            float4 e = __ldcs(&e4[i * 32 + lane]);
            float4 v = __ldg(&v4[i * 32 + lane]);
            acc += e.x * v.x + e.y * v.y + e.z * v.z + e.w * v.w;
        }
#pragma unroll
        for (int off = 16; off > 0; off >>= 1)
            acc += __shfl_xor_sync(0xFFFFFFFFu, acc, off);
        if (lane == 0) g_energy[r] = acc;
    }
}

// ---------------------------------------------------------------------------
// Kernel 3a: softmax phase 1 — per-chunk (m,s). grid (B, SCHUNK), block 256,
// 2 elems/thread. 256 CTAs spread over the chip (the single-kernel version
// used only 32 CTAs -> 120 idle SMs).
// ---------------------------------------------------------------------------
__global__ __launch_bounds__(256) void k_soft1() {
    const int b    = blockIdx.x;
    const int c    = blockIdx.y;
    const int tid  = threadIdx.x;
    const int base = b * S + c * 512;
    __shared__ float red_m[8], red_s[8];

    float e0 = g_energy[base + tid];
    float e1 = g_energy[base + 256 + tid];
    float m  = fmaxf(e0, e1);
    float s  = __expf(e0 - m) + __expf(e1 - m);

#pragma unroll
    for (int off = 16; off > 0; off >>= 1) {
        float mo = __shfl_xor_sync(0xFFFFFFFFu, m, off);
        float so = __shfl_xor_sync(0xFFFFFFFFu, s, off);
        float M  = fmaxf(m, mo);
        s = s * __expf(m - M) + so * __expf(mo - M);
        m = M;
    }
    if ((tid & 31) == 0) { red_m[tid >> 5] = m; red_s[tid >> 5] = s; }
    __syncthreads();
    if (tid == 0) {
        float mm = red_m[0], ss = red_s[0];
#pragma unroll
        for (int w = 1; w < 8; ++w) {
            float M = fmaxf(mm, red_m[w]);
            ss = ss * __expf(mm - M) + red_s[w] * __expf(red_m[w] - M);
            mm = M;
        }
        g_pm[b][c] = mm;
        g_ps[b][c] = ss;
    }
}

// ---------------------------------------------------------------------------
// Kernel 3b: softmax phase 2 — merge the SCHUNK (m,s) pairs (deterministic
// sequential order) and normalize. grid (B, SCHUNK), block 256.
// ---------------------------------------------------------------------------
__global__ __launch_bounds__(256) void k_soft2(float* __restrict__ out) {
    const int b    = blockIdx.x;
    const int c    = blockIdx.y;
    const int tid  = threadIdx.x;
    const int base = b * S + c * 512;
    __shared__ float sM, sI;

    if (tid == 0) {
        float mm = g_pm[b][0], ss = g_ps[b][0];
#pragma unroll
        for (int k = 1; k < SCHUNK; ++k) {
            float mk = g_pm[b][k];
            float M  = fmaxf(mm, mk);
            ss = ss * __expf(mm - M) + g_ps[b][k] * __expf(mk - M);
            mm = M;
        }
        sM = mm;
        sI = 1.0f / ss;
    }
    __syncthreads();
    const float M = sM, inv = sI;

    float e0 = g_energy[base + tid];
    float e1 = g_energy[base + 256 + tid];
    out[base + tid]       = __expf(e0 - M) * inv;
    out[base + 256 + tid] = __expf(e1 - M) * inv;
}

// ---------------------------------------------------------------------------
extern "C" void kernel_launch(void* const* d_in, const int* in_sizes, int n_in,
                              void* d_out, int out_size) {
    const float* hidden = (const float*)d_in[0];   // [B,H]
    const float* enc    = (const float*)d_in[1];   // [B,S,2H]
    const float* W      = (const float*)d_in[2];   // [H,2H]
    // d_in[3] = bias: constant per row -> cancels in softmax, unused.
    float* out = (float*)d_out;                    // [B,1,S]

    k_vpart<<<dim3(D / 128, B / BG, HS), 128>>>(hidden, W);
    k_vreduce<<<(B * D / 4 + 255) / 256, 256>>>();
    k_energy<<<NCTA_E, 512>>>(enc);
    k_soft1<<<dim3(B, SCHUNK), 256>>>();
    k_soft2<<<dim3(B, SCHUNK), 256>>>(out);
}